// round 2
// baseline (speedup 1.0000x reference)
#include <cuda_runtime.h>
#include <cuda_fp16.h>
#include <math.h>
#include <stdint.h>

// Problem dims
#define BB   64
#define TT   512
#define INS  512
#define HH   1024
#define G4   4096          // 4*HH
#define TB   (TT*BB)       // 32768

// Recurrence kernel config
#define NCTA_REC 128
#define JT       8         // hidden units per CTA (HH / NCTA_REC)
#define HS       (HH+8)    // padded smem row stride (fp16) -> conflict-free mma frag loads

// ---------------------------------------------------------------------------
// Scratch (device globals; no allocation allowed)
// ---------------------------------------------------------------------------
__device__ __align__(128) __half d_xb[TB*INS];         // x transposed to [t,b,k], fp16
__device__ __align__(128) __half d_wih0[G4*INS];
__device__ __align__(128) __half d_whh0[G4*HH];
__device__ __align__(128) __half d_wih1[G4*HH];
__device__ __align__(128) __half d_whh1[G4*HH];
__device__ __align__(128) float  d_gx[(size_t)TB*G4];  // 512MB, reused by both layers
__device__ __align__(128) __half d_h1[(size_t)TB*HH];  // layer0 outputs
__device__ __align__(128) __half d_h2[(size_t)TB*HH];  // layer1 outputs
__device__ __align__(128) __half d_hping[2*BB*HH];     // ping-pong recurrent h
__device__ unsigned d_bar_count;
__device__ unsigned d_bar_epoch;

// ---------------------------------------------------------------------------
// Helpers
// ---------------------------------------------------------------------------
__device__ __forceinline__ void mma16816(float* d, const uint32_t* a, uint32_t b0, uint32_t b1) {
    asm volatile(
        "mma.sync.aligned.m16n8k16.row.col.f32.f16.f16.f32 "
        "{%0,%1,%2,%3},{%4,%5,%6,%7},{%8,%9},{%0,%1,%2,%3};\n"
        : "+f"(d[0]), "+f"(d[1]), "+f"(d[2]), "+f"(d[3])
        : "r"(a[0]), "r"(a[1]), "r"(a[2]), "r"(a[3]), "r"(b0), "r"(b1));
}

__device__ __forceinline__ float sigf(float x) { return 1.0f / (1.0f + expf(-x)); }

__device__ __forceinline__ uint32_t lds32(const __half* p) {
    return *reinterpret_cast<const uint32_t*>(p);
}

// ---------------------------------------------------------------------------
// Conversions
// ---------------------------------------------------------------------------
__global__ void k_conv(const float* __restrict__ src, __half* __restrict__ dst, int n) {
    int i = blockIdx.x * blockDim.x + threadIdx.x;
    if (i < n) dst[i] = __float2half(src[i]);
}

// x: [B,T,IN] fp32 -> xb: [T*B, IN] fp16 (t-major rows)
__global__ void k_conv_x(const float* __restrict__ x, __half* __restrict__ xb) {
    int i = blockIdx.x * blockDim.x + threadIdx.x;   // over 2^24 elements
    int k = i & (INS - 1);
    int t = (i >> 9) & (TT - 1);
    int b = i >> 18;
    xb[(size_t)(t * BB + b) * INS + k] = __float2half(x[i]);
}

// ---------------------------------------------------------------------------
// Batched GEMM: C[M,N] fp32 = A[M,K]fp16 @ B[N,K]fp16^T + bias1[n] + bias2[n]
// BM=128, BN=128, BK=64; 256 threads = 8 warps (2x4), warp tile 64x32.
// ---------------------------------------------------------------------------
#define BM 128
#define BN 128
#define BK 64
#define KP 72   // padded k stride

__global__ __launch_bounds__(256) void k_gemm_bias(
    const __half* __restrict__ A,
    const __half* __restrict__ Bw,
    const float* __restrict__ bias1,
    const float* __restrict__ bias2,
    float* __restrict__ C, int M, int N, int K)
{
    __shared__ __half sA[BM * KP];
    __shared__ __half sB[BN * KP];

    const int bm = blockIdx.x * BM;
    const int bn = blockIdx.y * BN;
    const int tid  = threadIdx.x;
    const int w    = tid >> 5, lane = tid & 31;
    const int gid  = lane >> 2, lg = lane & 3;
    const int wm   = w >> 2, wn = w & 3;
    const int m0   = wm * 64, n0 = wn * 32;

    float acc[4][4][4];
    #pragma unroll
    for (int mt = 0; mt < 4; mt++)
        #pragma unroll
        for (int nt = 0; nt < 4; nt++)
            #pragma unroll
            for (int r = 0; r < 4; r++) acc[mt][nt][r] = 0.0f;

    for (int kc = 0; kc < K; kc += BK) {
        __syncthreads();
        #pragma unroll
        for (int i = 0; i < 4; i++) {
            int idx = tid + i * 256;            // 0..1023
            int row = idx >> 3, c8 = idx & 7;   // 128 rows x 8 chunks of 8 fp16
            *reinterpret_cast<uint4*>(&sA[row * KP + c8 * 8]) =
                *reinterpret_cast<const uint4*>(&A[(size_t)(bm + row) * K + kc + c8 * 8]);
            *reinterpret_cast<uint4*>(&sB[row * KP + c8 * 8]) =
                *reinterpret_cast<const uint4*>(&Bw[(size_t)(bn + row) * K + kc + c8 * 8]);
        }
        __syncthreads();

        #pragma unroll
        for (int ks = 0; ks < BK / 16; ks++) {
            const int kb = ks * 16 + lg * 2;
            uint32_t a[4][4];
            #pragma unroll
            for (int mt = 0; mt < 4; mt++) {
                int r1 = m0 + mt * 16 + gid;
                a[mt][0] = lds32(&sA[r1 * KP + kb]);
                a[mt][1] = lds32(&sA[(r1 + 8) * KP + kb]);
                a[mt][2] = lds32(&sA[r1 * KP + kb + 8]);
                a[mt][3] = lds32(&sA[(r1 + 8) * KP + kb + 8]);
            }
            #pragma unroll
            for (int nt = 0; nt < 4; nt++) {
                int rn = n0 + nt * 8 + gid;
                uint32_t b0 = lds32(&sB[rn * KP + kb]);
                uint32_t b1 = lds32(&sB[rn * KP + kb + 8]);
                #pragma unroll
                for (int mt = 0; mt < 4; mt++)
                    mma16816(acc[mt][nt], a[mt], b0, b1);
            }
        }
    }

    #pragma unroll
    for (int mt = 0; mt < 4; mt++) {
        #pragma unroll
        for (int nt = 0; nt < 4; nt++) {
            int gm1 = bm + m0 + mt * 16 + gid;
            int gn  = bn + n0 + nt * 8 + lg * 2;
            float bi0 = bias1[gn] + bias2[gn];
            float bi1 = bias1[gn + 1] + bias2[gn + 1];
            float2 v0 = make_float2(acc[mt][nt][0] + bi0, acc[mt][nt][1] + bi1);
            float2 v1 = make_float2(acc[mt][nt][2] + bi0, acc[mt][nt][3] + bi1);
            *reinterpret_cast<float2*>(&C[(size_t)gm1 * N + gn]) = v0;
            *reinterpret_cast<float2*>(&C[(size_t)(gm1 + 8) * N + gn]) = v1;
        }
    }
}

// ---------------------------------------------------------------------------
// Persistent LSTM recurrence. 128 CTAs x 256 threads, one wave (1 CTA/SM via
// smem). CTA owns 8 hidden units (32 gate rows). w_hh slice lives in smem for
// all 512 steps. One software grid barrier per step; h ping-pongs in global.
// GEMM per step: M=64, N=32, K=1024 via mma.sync, K split across warp halves.
// ---------------------------------------------------------------------------
__global__ __launch_bounds__(256) void k_lstm_rec(
    const float* __restrict__ gx,           // [T*B, 4096]
    const __half* __restrict__ whh,         // [4096, 1024] fp16
    __half* __restrict__ hall)              // [T*B, H] fp16
{
    extern __shared__ __align__(16) char smem[];
    __half* wsm = reinterpret_cast<__half*>(smem);   // 32 * HS
    __half* hsm = wsm + 32 * HS;                     // 64 * HS
    float* gsm = reinterpret_cast<float*>(hsm + 64 * HS);          // 64 * 33
    float* csm = gsm + 64 * 33;                                    // 512

    const int tid = threadIdx.x;
    const int cta = blockIdx.x;
    const int j0  = cta * JT;
    const int lane = tid & 31, w = tid >> 5;
    const int gid = lane >> 2, lg = lane & 3;
    const int kh = w >> 2;            // k half: 0 or 1
    const int m0 = (w & 3) * 16;      // m tile base

    // Load this CTA's 32 gate rows of w_hh into smem (once).
    #pragma unroll
    for (int i = 0; i < 16; i++) {
        int idx = tid + i * 256;            // 0..4095
        int row = idx >> 7, c8 = idx & 127; // 32 rows x 128 chunks of 8
        int grow = (row >> 3) * HH + j0 + (row & 7);
        *reinterpret_cast<uint4*>(&wsm[row * HS + c8 * 8]) =
            *reinterpret_cast<const uint4*>(&whh[(size_t)grow * HH + c8 * 8]);
    }
    for (int i = tid; i < 512; i += 256) csm[i] = 0.0f;

    __shared__ unsigned s_epoch;
    if (tid == 0) s_epoch = *(volatile unsigned*)&d_bar_epoch;
    __syncthreads();
    unsigned bar_target = s_epoch;

    for (int t = 0; t < TT; t++) {
        const __half* hcur = d_hping + (size_t)(t & 1) * (BB * HH);
        __half* hnext      = d_hping + (size_t)((t + 1) & 1) * (BB * HH);

        // Prefetch gx epilogue values (kh==0 warps own the epilogue).
        float gxr[4][4];
        if (kh == 0) {
            const float* gp = gx + (size_t)(t * BB) * G4;
            int r1 = m0 + gid;
            #pragma unroll
            for (int nt = 0; nt < 4; nt++) {
                int gn = nt * HH + j0 + lg * 2;
                gxr[nt][0] = gp[(size_t)r1 * G4 + gn];
                gxr[nt][1] = gp[(size_t)r1 * G4 + gn + 1];
                gxr[nt][2] = gp[(size_t)(r1 + 8) * G4 + gn];
                gxr[nt][3] = gp[(size_t)(r1 + 8) * G4 + gn + 1];
            }
        }

        // Stage h(t) into smem.
        if (t == 0) {
            for (int i = tid; i < 64 * HS / 8; i += 256)
                *reinterpret_cast<uint4*>(&hsm[i * 8]) = make_uint4(0, 0, 0, 0);
        } else {
            #pragma unroll
            for (int i = 0; i < 32; i++) {
                int idx = tid + i * 256;            // 0..8191
                int row = idx >> 7, c8 = idx & 127;
                *reinterpret_cast<uint4*>(&hsm[row * HS + c8 * 8]) =
                    *reinterpret_cast<const uint4*>(&hcur[(size_t)row * HH + c8 * 8]);
            }
        }
        __syncthreads();

        // gates(hh part): [64 x 32] = hsm[64 x 1024] @ wsm[32 x 1024]^T
        float acc[4][4];
        #pragma unroll
        for (int nt = 0; nt < 4; nt++)
            #pragma unroll
            for (int r = 0; r < 4; r++) acc[nt][r] = 0.0f;

        const int kbase = kh * 512;
        #pragma unroll 8
        for (int ks = 0; ks < 32; ks++) {
            const int kb = kbase + ks * 16 + lg * 2;
            uint32_t a[4];
            a[0] = lds32(&hsm[(m0 + gid) * HS + kb]);
            a[1] = lds32(&hsm[(m0 + gid + 8) * HS + kb]);
            a[2] = lds32(&hsm[(m0 + gid) * HS + kb + 8]);
            a[3] = lds32(&hsm[(m0 + gid + 8) * HS + kb + 8]);
            #pragma unroll
            for (int nt = 0; nt < 4; nt++) {
                uint32_t b0 = lds32(&wsm[(nt * 8 + gid) * HS + kb]);
                uint32_t b1 = lds32(&wsm[(nt * 8 + gid) * HS + kb + 8]);
                mma16816(acc[nt], a, b0, b1);
            }
        }

        // K-split reduction + gx add -> gsm
        if (kh == 1) {
            #pragma unroll
            for (int nt = 0; nt < 4; nt++) {
                int col = nt * 8 + lg * 2;
                gsm[(m0 + gid) * 33 + col]       = acc[nt][0];
                gsm[(m0 + gid) * 33 + col + 1]   = acc[nt][1];
                gsm[(m0 + gid + 8) * 33 + col]     = acc[nt][2];
                gsm[(m0 + gid + 8) * 33 + col + 1] = acc[nt][3];
            }
        }
        __syncthreads();
        if (kh == 0) {
            #pragma unroll
            for (int nt = 0; nt < 4; nt++) {
                int col = nt * 8 + lg * 2;
                int o00 = (m0 + gid) * 33 + col;
                int o10 = (m0 + gid + 8) * 33 + col;
                gsm[o00]     = acc[nt][0] + gsm[o00]     + gxr[nt][0];
                gsm[o00 + 1] = acc[nt][1] + gsm[o00 + 1] + gxr[nt][1];
                gsm[o10]     = acc[nt][2] + gsm[o10]     + gxr[nt][2];
                gsm[o10 + 1] = acc[nt][3] + gsm[o10 + 1] + gxr[nt][3];
            }
        }
        __syncthreads();

        // Pointwise LSTM cell: 512 (b, jj) pairs, 2 per thread.
        #pragma unroll
        for (int r = 0; r < 2; r++) {
            int idx = tid + r * 256;
            int b = idx >> 3, jj = idx & 7;
            float iv = gsm[b * 33 + jj];
            float fv = gsm[b * 33 + 8 + jj];
            float gv = gsm[b * 33 + 16 + jj];
            float ov = gsm[b * 33 + 24 + jj];
            float c = sigf(fv) * csm[idx] + sigf(iv) * tanhf(gv);
            csm[idx] = c;
            float h = sigf(ov) * tanhf(c);
            __half hb = __float2half(h);
            hnext[(size_t)b * HH + j0 + jj] = hb;
            hall[((size_t)(t * BB) + b) * HH + j0 + jj] = hb;
        }

        // Grid-wide barrier (epoch-based, replay-safe).
        __threadfence();
        __syncthreads();
        if (tid == 0) {
            bar_target++;
            unsigned old = atomicAdd(&d_bar_count, 1);
            if (old == NCTA_REC - 1) {
                d_bar_count = 0;
                __threadfence();
                atomicAdd(&d_bar_epoch, 1);
            } else {
                while ((int)(*(volatile unsigned*)&d_bar_epoch - bar_target) < 0) { }
            }
            __threadfence();
        }
        __syncthreads();
    }
}

// ---------------------------------------------------------------------------
// Output projection: one warp per (t, b): out[b*T + t] = dot(h2[t,b,:], w_out) + b_out
// ---------------------------------------------------------------------------
__global__ void k_out(const __half* __restrict__ h2,
                      const float* __restrict__ wout,
                      const float* __restrict__ bout,
                      float* __restrict__ out)
{
    int wg = (blockIdx.x * blockDim.x + threadIdx.x) >> 5;
    int lane = threadIdx.x & 31;
    if (wg >= TB) return;
    int t = wg >> 6;     // / BB
    int b = wg & 63;
    const __half* hp = h2 + (size_t)wg * HH;
    float sum = 0.0f;
    #pragma unroll
    for (int i = 0; i < 4; i++) {
        int k = i * 256 + lane * 8;
        uint4 v = *reinterpret_cast<const uint4*>(&hp[k]);
        const __half* pv = reinterpret_cast<const __half*>(&v);
        float4 w0 = *reinterpret_cast<const float4*>(&wout[k]);
        float4 w1 = *reinterpret_cast<const float4*>(&wout[k + 4]);
        sum += __half2float(pv[0]) * w0.x + __half2float(pv[1]) * w0.y
             + __half2float(pv[2]) * w0.z + __half2float(pv[3]) * w0.w
             + __half2float(pv[4]) * w1.x + __half2float(pv[5]) * w1.y
             + __half2float(pv[6]) * w1.z + __half2float(pv[7]) * w1.w;
    }
    #pragma unroll
    for (int off = 16; off; off >>= 1) sum += __shfl_xor_sync(0xffffffffu, sum, off);
    if (lane == 0) out[(size_t)b * TT + t] = sum + bout[0];
}

// ---------------------------------------------------------------------------
// Launch
// ---------------------------------------------------------------------------
extern "C" void kernel_launch(void* const* d_in, const int* in_sizes, int n_in,
                              void* d_out, int out_size)
{
    const float* x     = (const float*)d_in[0];
    const float* w_ih0 = (const float*)d_in[1];
    const float* w_hh0 = (const float*)d_in[2];
    const float* b_ih0 = (const float*)d_in[3];
    const float* b_hh0 = (const float*)d_in[4];
    const float* w_ih1 = (const float*)d_in[5];
    const float* w_hh1 = (const float*)d_in[6];
    const float* b_ih1 = (const float*)d_in[7];
    const float* b_hh1 = (const float*)d_in[8];
    const float* w_out = (const float*)d_in[9];
    const float* b_out = (const float*)d_in[10];
    float* out = (float*)d_out;

    void *p_xb, *p_wih0, *p_whh0, *p_wih1, *p_whh1, *p_gx, *p_h1, *p_h2;
    cudaGetSymbolAddress(&p_xb, d_xb);
    cudaGetSymbolAddress(&p_wih0, d_wih0);
    cudaGetSymbolAddress(&p_whh0, d_whh0);
    cudaGetSymbolAddress(&p_wih1, d_wih1);
    cudaGetSymbolAddress(&p_whh1, d_whh1);
    cudaGetSymbolAddress(&p_gx, d_gx);
    cudaGetSymbolAddress(&p_h1, d_h1);
    cudaGetSymbolAddress(&p_h2, d_h2);

    const int SMEM_REC = (32 + 64) * HS * 2 + 64 * 33 * 4 + 512 * 4;   // 208640
    cudaFuncSetAttribute(k_lstm_rec, cudaFuncAttributeMaxDynamicSharedMemorySize, SMEM_REC);

    // Conversions
    k_conv_x<<<(TB * INS) / 256, 256>>>(x, (__half*)p_xb);
    k_conv<<<(G4 * INS) / 256, 256>>>(w_ih0, (__half*)p_wih0, G4 * INS);
    k_conv<<<(G4 * HH) / 256, 256>>>(w_hh0, (__half*)p_whh0, G4 * HH);
    k_conv<<<(G4 * HH) / 256, 256>>>(w_ih1, (__half*)p_wih1, G4 * HH);
    k_conv<<<(G4 * HH) / 256, 256>>>(w_hh1, (__half*)p_whh1, G4 * HH);

    dim3 gg(TB / BM, G4 / BN);

    // Layer 0: gx0 = x @ w_ih0^T + b_ih0 + b_hh0 ; recurrence -> h1
    k_gemm_bias<<<gg, 256>>>((__half*)p_xb, (__half*)p_wih0,
                             b_ih0, b_hh0, (float*)p_gx, TB, G4, INS);
    k_lstm_rec<<<NCTA_REC, 256, SMEM_REC>>>((float*)p_gx, (__half*)p_whh0,
                                            (__half*)p_h1);

    // Layer 1: gx1 = h1 @ w_ih1^T + b_ih1 + b_hh1 ; recurrence -> h2
    k_gemm_bias<<<gg, 256>>>((__half*)p_h1, (__half*)p_wih1,
                             b_ih1, b_hh1, (float*)p_gx, TB, G4, HH);
    k_lstm_rec<<<NCTA_REC, 256, SMEM_REC>>>((float*)p_gx, (__half*)p_whh1,
                                            (__half*)p_h2);

    // Output projection
    k_out<<<(TB * 32) / 256, 256>>>((__half*)p_h2, w_out, b_out, out);
}